// round 9
// baseline (speedup 1.0000x reference)
#include <cuda_runtime.h>
#include <math.h>

#define N_NODES 100000
#define N_EDGES 1600000
#define F_IN    128
#define F_HID   64
#define BN_EPS  1e-5f

// ------------------------- scratch (__device__ globals) --------------------
__device__ float g_bufA[(size_t)N_NODES * F_HID];
__device__ float g_bufB[(size_t)N_NODES * F_HID];
__device__ float g_dinv[N_NODES];
__device__ int   g_cnt[N_NODES];
__device__ int   g_rowptr[N_NODES + 1];
__device__ int   g_cursor[N_NODES];
__device__ int2  g_epair[N_EDGES];                 // (src, norm-as-int)
__device__ int   g_blksum[128];

// ------------------------- cp.async helpers --------------------------------
__device__ __forceinline__ void cp_async16(void* smem_dst, const void* gmem_src) {
    unsigned s = (unsigned)__cvta_generic_to_shared(smem_dst);
    asm volatile("cp.async.cg.shared.global [%0], [%1], 16;\n"
                 :: "r"(s), "l"(gmem_src));
}
__device__ __forceinline__ void cp_commit() {
    asm volatile("cp.async.commit_group;\n");
}
template <int N>
__device__ __forceinline__ void cp_wait() {
    asm volatile("cp.async.wait_group %0;\n" :: "n"(N));
}

// ------------------------- GEMM: out[N,64] = x[N,KDIM] @ W[KDIM,64] --------
// 256 threads/block, tile 128 nodes x 64 feats; thread = 8 nodes x 4 feats.
// W staged whole once; X chunks (row-major, stride 36) double-buffered with
// cp.async overlapping compute. Dynamic smem.
#define XSTRIDE 36

template <int KDIM>
__global__ void __launch_bounds__(256, 3)
k_gemm(const float* __restrict__ x, const float* __restrict__ W,
       float* __restrict__ out) {
    extern __shared__ __align__(16) float smem[];
    float* Ws  = smem;                        // KDIM*64 floats
    float* Xs0 = smem + KDIM * 64;            // 128*XSTRIDE
    float* Xs1 = Xs0 + 128 * XSTRIDE;

    const int C = KDIM / 32;                  // k-chunks
    int tid  = threadIdx.x;
    int fgrp = tid & 15;                      // 16 feat groups x 4 feats
    int ngrp = tid >> 4;                      // 16 node groups
    int nodeBase = blockIdx.x * 128;

    float4 acc[8];
#pragma unroll
    for (int a = 0; a < 8; a++) acc[a] = make_float4(0.f, 0.f, 0.f, 0.f);

    // prefetch X chunk 0 + all of W (one group)
    {
        float* Xb = Xs0;
#pragma unroll
        for (int t = 0; t < 4; t++) {
            int i = t * 256 + tid;
            int node = i >> 3, q = i & 7;
            int gn = nodeBase + node;
            if (gn >= N_NODES) gn = N_NODES - 1;
            cp_async16(Xb + node * XSTRIDE + q * 4,
                       x + (size_t)gn * KDIM + q * 4);
        }
        for (int i = tid; i < KDIM * 16; i += 256)
            cp_async16(Ws + i * 4, W + i * 4);
        cp_commit();
    }

    for (int c = 0; c < C; c++) {
        if (c + 1 < C) {                       // prefetch next chunk
            float* Xb = ((c + 1) & 1) ? Xs1 : Xs0;
#pragma unroll
            for (int t = 0; t < 4; t++) {
                int i = t * 256 + tid;
                int node = i >> 3, q = i & 7;
                int gn = nodeBase + node;
                if (gn >= N_NODES) gn = N_NODES - 1;
                cp_async16(Xb + node * XSTRIDE + q * 4,
                           x + (size_t)gn * KDIM + (c + 1) * 32 + q * 4);
            }
            cp_commit();
            cp_wait<1>();
        } else {
            cp_wait<0>();
        }
        __syncthreads();

        const float* Xb = (c & 1) ? Xs1 : Xs0;
#pragma unroll
        for (int kkg = 0; kkg < 8; kkg++) {
            float4 xr[8];
#pragma unroll
            for (int nn = 0; nn < 8; nn++)
                xr[nn] = *reinterpret_cast<const float4*>(
                    Xb + (nn * 16 + ngrp) * XSTRIDE + kkg * 4);
#pragma unroll
            for (int j = 0; j < 4; j++) {
                float4 w = *reinterpret_cast<const float4*>(
                    Ws + (c * 32 + kkg * 4 + j) * 64 + fgrp * 4);
#pragma unroll
                for (int nn = 0; nn < 8; nn++) {
                    float xs = (j == 0) ? xr[nn].x : (j == 1) ? xr[nn].y
                             : (j == 2) ? xr[nn].z : xr[nn].w;
                    acc[nn].x += xs * w.x; acc[nn].y += xs * w.y;
                    acc[nn].z += xs * w.z; acc[nn].w += xs * w.w;
                }
            }
        }
        __syncthreads();
    }

#pragma unroll
    for (int nn = 0; nn < 8; nn++) {
        int n = nodeBase + nn * 16 + ngrp;
        if (n < N_NODES)
            *reinterpret_cast<float4*>(out + (size_t)n * 64 + fgrp * 4) = acc[nn];
    }
}

// ------------------------- CSR build --------------------------------------
__global__ void k_zero_cnt() {
    int i = blockIdx.x * blockDim.x + threadIdx.x;
    if (i < N_NODES) g_cnt[i] = 0;
}

__global__ void k_hist(const int* __restrict__ ei) {
    int e = blockIdx.x * blockDim.x + threadIdx.x;
    if (e < N_EDGES) atomicAdd(&g_cnt[ei[N_EDGES + e]], 1);
}

// per-block inclusive scan of g_cnt -> g_rowptr[i+1]; also dinv = rsqrt(cnt+1)
__global__ void k_scan1() {
    __shared__ int wsum[32];
    int i = blockIdx.x * 1024 + threadIdx.x;
    int lane = threadIdx.x & 31, wid = threadIdx.x >> 5;
    int v = (i < N_NODES) ? g_cnt[i] : 0;
    if (i < N_NODES) g_dinv[i] = rsqrtf((float)v + 1.0f);
    int sv = v;
#pragma unroll
    for (int d = 1; d < 32; d <<= 1) {
        int t = __shfl_up_sync(0xffffffffu, sv, d);
        if (lane >= d) sv += t;
    }
    if (lane == 31) wsum[wid] = sv;
    __syncthreads();
    if (wid == 0) {
        int wv = wsum[lane];
#pragma unroll
        for (int d = 1; d < 32; d <<= 1) {
            int t = __shfl_up_sync(0xffffffffu, wv, d);
            if (lane >= d) wv += t;
        }
        wsum[lane] = wv;
    }
    __syncthreads();
    int incl = sv + (wid > 0 ? wsum[wid - 1] : 0);
    if (i < N_NODES) g_rowptr[i + 1] = incl;
    if (threadIdx.x == 1023) g_blksum[blockIdx.x] = incl;
}

__global__ void k_scan2(int nb) {
    __shared__ int wsum[4];
    int b = threadIdx.x;
    int lane = b & 31, wid = b >> 5;
    int v = (b < nb) ? g_blksum[b] : 0;
    int sv = v;
#pragma unroll
    for (int d = 1; d < 32; d <<= 1) {
        int t = __shfl_up_sync(0xffffffffu, sv, d);
        if (lane >= d) sv += t;
    }
    if (lane == 31) wsum[wid] = sv;
    __syncthreads();
    if (b == 0) {
        int run = 0;
#pragma unroll
        for (int w = 0; w < 4; w++) { int t = wsum[w]; wsum[w] = run; run += t; }
    }
    __syncthreads();
    int excl = sv + wsum[wid] - v;
    if (b < nb) g_blksum[b] = excl;
}

// finalize rowptr AND init cursor
__global__ void k_scan3() {
    int i = blockIdx.x * blockDim.x + threadIdx.x;
    if (i < N_NODES) {
        int rp = g_rowptr[i + 1] + g_blksum[i >> 10];
        g_rowptr[i + 1] = rp;
        if (i + 1 < N_NODES) g_cursor[i + 1] = rp;
    }
    if (i == 0) { g_rowptr[0] = 0; g_cursor[0] = 0; }
}

__global__ void k_fill(const int* __restrict__ ei) {
    int e = blockIdx.x * blockDim.x + threadIdx.x;
    if (e >= N_EDGES) return;
    int s = ei[e];
    int d = ei[N_EDGES + e];
    int pos = atomicAdd(&g_cursor[d], 1);
    float w = g_dinv[s] * g_dinv[d];
    g_epair[pos] = make_int2(s, __float_as_int(w));
}

// ------------------------- fused gather + self + BN + ReLU (+ head) --------
// One warp per node. Lane holds features (2*lane, 2*lane+1) as float2.
// 16-edge chunks: 16 independent row loads in flight per warp.
template <bool HEAD>
__global__ void k_gather(const float* __restrict__ h,
                         const float* __restrict__ bb, const float* __restrict__ gg,
                         const float* __restrict__ be, const float* __restrict__ mm,
                         const float* __restrict__ vv,
                         const float* __restrict__ Wc1, const float* __restrict__ bc1,
                         const float* __restrict__ Wc2, const float* __restrict__ bc2,
                         float* __restrict__ out) {
    __shared__ float W1s[64 * 32];
    int tid = threadIdx.x, lane = tid & 31, warp = tid >> 5;
    if (HEAD) {
        for (int i = tid; i < 64 * 32; i += 256) W1s[i] = Wc1[i];
        __syncthreads();
    }
    int n = blockIdx.x * 8 + warp;
    if (n >= N_NODES) return;

    const float2* __restrict__ h2 = reinterpret_cast<const float2*>(h);
    int beg = g_rowptr[n], end = g_rowptr[n + 1];
    float di = g_dinv[n];

    float2 hv = __ldg(h2 + (size_t)n * 32 + lane);
    float accx = di * di * hv.x;
    float accy = di * di * hv.y;

    for (int p = beg; p < end; p += 16) {
        int2 eb[16];
#pragma unroll
        for (int j = 0; j < 16; j++) {
            int idx = p + j;
            eb[j] = (idx < end) ? __ldg(&g_epair[idx]) : make_int2(0, 0);
        }
#pragma unroll
        for (int j = 0; j < 16; j++) {
            float w = __int_as_float(eb[j].y);
            float2 hs = __ldg(h2 + (size_t)eb[j].x * 32 + lane);
            accx += w * hs.x;
            accy += w * hs.y;
        }
    }

    int f0 = 2 * lane, f1 = 2 * lane + 1;
    float sc0 = __ldg(gg + f0) * rsqrtf(__ldg(vv + f0) + BN_EPS);
    float sc1 = __ldg(gg + f1) * rsqrtf(__ldg(vv + f1) + BN_EPS);
    float val0 = fmaxf((accx + __ldg(bb + f0) - __ldg(mm + f0)) * sc0 + __ldg(be + f0), 0.0f);
    float val1 = fmaxf((accy + __ldg(bb + f1) - __ldg(mm + f1)) * sc1 + __ldg(be + f1), 0.0f);

    if (!HEAD) {
        reinterpret_cast<float2*>(out)[(size_t)n * 32 + lane] = make_float2(val0, val1);
    } else {
        float a = __ldg(bc1 + lane);
#pragma unroll
        for (int k = 0; k < 32; k++) {
            a += __shfl_sync(0xffffffffu, val0, k) * W1s[(2 * k)     * 32 + lane];
            a += __shfl_sync(0xffffffffu, val1, k) * W1s[(2 * k + 1) * 32 + lane];
        }
        float mid = fmaxf(a, 0.0f);
        float pp = mid * __ldg(Wc2 + lane);
#pragma unroll
        for (int off = 16; off; off >>= 1)
            pp += __shfl_xor_sync(0xffffffffu, pp, off);
        if (lane == 0)
            out[n] = 1.0f / (1.0f + expf(-(pp + __ldg(bc2))));
    }
}

// ---------------------------------------------------------------------------
extern "C" void kernel_launch(void* const* d_in, const int* in_sizes, int n_in,
                              void* d_out, int out_size) {
    const float* x   = (const float*)d_in[0];
    const int*   ei  = (const int*)  d_in[1];
    const float* W1  = (const float*)d_in[2];
    const float* b1  = (const float*)d_in[3];
    const float* g1  = (const float*)d_in[4];
    const float* be1 = (const float*)d_in[5];
    const float* m1  = (const float*)d_in[6];
    const float* v1  = (const float*)d_in[7];
    const float* W2  = (const float*)d_in[8];
    const float* b2  = (const float*)d_in[9];
    const float* g2  = (const float*)d_in[10];
    const float* be2 = (const float*)d_in[11];
    const float* m2  = (const float*)d_in[12];
    const float* v2  = (const float*)d_in[13];
    const float* Wc1 = (const float*)d_in[14];
    const float* bc1 = (const float*)d_in[15];
    const float* Wc2 = (const float*)d_in[16];
    const float* bc2 = (const float*)d_in[17];
    float* out = (float*)d_out;

    float* bufA;  cudaGetSymbolAddress((void**)&bufA, g_bufA);
    float* bufB;  cudaGetSymbolAddress((void**)&bufB, g_bufB);

    // Lazy one-time creation of side stream + fork/join events (created on the
    // uncaptured correctness call; only record/wait — both capture-legal —
    // happen during capture). No device memory involved.
    static cudaStream_t s_side = nullptr;
    static cudaEvent_t  s_fork = nullptr, s_join = nullptr;
    if (s_side == nullptr) {
        cudaStreamCreateWithFlags(&s_side, cudaStreamNonBlocking);
        cudaEventCreateWithFlags(&s_fork, cudaEventDisableTiming);
        cudaEventCreateWithFlags(&s_join, cudaEventDisableTiming);
    }

    const int nodeBlocks = (N_NODES + 255) / 256;            // 391
    const int edgeBlocks = (N_EDGES + 255) / 256;            // 6250
    const int scanBlocks = (N_NODES + 1023) / 1024;          // 98
    const int gemmBlocks = (N_NODES + 127) / 128;            // 782
    const int gathBlocks = (N_NODES + 7) / 8;                // 12500

    const int smem1 = (F_IN  * 64 + 2 * 128 * XSTRIDE) * 4;  // 69632 B
    const int smem2 = (F_HID * 64 + 2 * 128 * XSTRIDE) * 4;  // 53248 B
    cudaFuncSetAttribute(k_gemm<F_IN>,
                         cudaFuncAttributeMaxDynamicSharedMemorySize, smem1);
    cudaFuncSetAttribute(k_gemm<F_HID>,
                         cudaFuncAttributeMaxDynamicSharedMemorySize, smem2);

    // Fork: gemm1 (needs only x,W1) runs on the side branch concurrently with
    // the CSR build on the main (capture) stream.
    cudaEventRecord(s_fork, 0);
    cudaStreamWaitEvent(s_side, s_fork, 0);
    k_gemm<F_IN><<<gemmBlocks, 256, smem1, s_side>>>(x, W1, bufA);
    cudaEventRecord(s_join, s_side);

    // Main branch: CSR build
    k_zero_cnt<<<nodeBlocks, 256>>>();
    k_hist<<<edgeBlocks, 256>>>(ei);
    k_scan1<<<scanBlocks, 1024>>>();
    k_scan2<<<1, 128>>>(scanBlocks);
    k_scan3<<<nodeBlocks, 256>>>();
    k_fill<<<edgeBlocks, 256>>>(ei);

    // Join: gather1 needs both bufA (side) and epair/rowptr (main)
    cudaStreamWaitEvent(0, s_join, 0);

    k_gather<false><<<gathBlocks, 256>>>(bufA, b1, g1, be1, m1, v1,
                                         nullptr, nullptr, nullptr, nullptr, bufB);
    k_gemm<F_HID><<<gemmBlocks, 256, smem2>>>(bufB, W2, bufA);
    k_gather<true><<<gathBlocks, 256>>>(bufA, b2, g2, be2, m2, v2,
                                        Wc1, bc1, Wc2, bc2, out);
}

// round 10
// speedup vs baseline: 1.0917x; 1.0917x over previous
#include <cuda_runtime.h>
#include <cuda_fp16.h>
#include <math.h>

#define N_NODES 100000
#define N_EDGES 1600000
#define F_IN    128
#define F_HID   64
#define BN_EPS  1e-5f

// ------------------------- scratch (__device__ globals) --------------------
__device__ __half g_bufH[(size_t)N_NODES * F_HID];  // 12.8 MB: h1 / h2 (fp16)
__device__ float  g_bufF[(size_t)N_NODES * F_HID];  // 25.6 MB: z1 (fp32)
__device__ float  g_dinv[N_NODES];
__device__ int    g_cnt[N_NODES];
__device__ int    g_rowptr[N_NODES + 1];
__device__ int    g_cursor[N_NODES];
__device__ int2   g_epair[N_EDGES];                 // (src, norm-as-int)
__device__ int    g_blksum[128];

// ------------------------- cp.async helpers --------------------------------
__device__ __forceinline__ void cp_async16(void* smem_dst, const void* gmem_src) {
    unsigned s = (unsigned)__cvta_generic_to_shared(smem_dst);
    asm volatile("cp.async.cg.shared.global [%0], [%1], 16;\n"
                 :: "r"(s), "l"(gmem_src));
}
__device__ __forceinline__ void cp_commit() {
    asm volatile("cp.async.commit_group;\n");
}
template <int N>
__device__ __forceinline__ void cp_wait() {
    asm volatile("cp.async.wait_group %0;\n" :: "n"(N));
}

// ------------------------- GEMM: out[N,64] = x[N,KDIM] @ W[KDIM,64] --------
// fp32 inputs, fp16 output. 256 threads/block, tile 128 nodes x 64 feats;
// thread = 8 nodes x 4 feats. W staged whole once; X chunks double-buffered
// via cp.async. Dynamic smem.
#define XSTRIDE 36

template <int KDIM>
__global__ void __launch_bounds__(256, 3)
k_gemm(const float* __restrict__ x, const float* __restrict__ W,
       __half* __restrict__ out) {
    extern __shared__ __align__(16) float smem[];
    float* Ws  = smem;                        // KDIM*64 floats
    float* Xs0 = smem + KDIM * 64;            // 128*XSTRIDE
    float* Xs1 = Xs0 + 128 * XSTRIDE;

    const int C = KDIM / 32;                  // k-chunks
    int tid  = threadIdx.x;
    int fgrp = tid & 15;                      // 16 feat groups x 4 feats
    int ngrp = tid >> 4;                      // 16 node groups
    int nodeBase = blockIdx.x * 128;

    float4 acc[8];
#pragma unroll
    for (int a = 0; a < 8; a++) acc[a] = make_float4(0.f, 0.f, 0.f, 0.f);

    // prefetch X chunk 0 + all of W (one group)
    {
        float* Xb = Xs0;
#pragma unroll
        for (int t = 0; t < 4; t++) {
            int i = t * 256 + tid;
            int node = i >> 3, q = i & 7;
            int gn = nodeBase + node;
            if (gn >= N_NODES) gn = N_NODES - 1;
            cp_async16(Xb + node * XSTRIDE + q * 4,
                       x + (size_t)gn * KDIM + q * 4);
        }
        for (int i = tid; i < KDIM * 16; i += 256)
            cp_async16(Ws + i * 4, W + i * 4);
        cp_commit();
    }

    for (int c = 0; c < C; c++) {
        if (c + 1 < C) {                       // prefetch next chunk
            float* Xb = ((c + 1) & 1) ? Xs1 : Xs0;
#pragma unroll
            for (int t = 0; t < 4; t++) {
                int i = t * 256 + tid;
                int node = i >> 3, q = i & 7;
                int gn = nodeBase + node;
                if (gn >= N_NODES) gn = N_NODES - 1;
                cp_async16(Xb + node * XSTRIDE + q * 4,
                           x + (size_t)gn * KDIM + (c + 1) * 32 + q * 4);
            }
            cp_commit();
            cp_wait<1>();
        } else {
            cp_wait<0>();
        }
        __syncthreads();

        const float* Xb = (c & 1) ? Xs1 : Xs0;
#pragma unroll
        for (int kkg = 0; kkg < 8; kkg++) {
            float4 xr[8];
#pragma unroll
            for (int nn = 0; nn < 8; nn++)
                xr[nn] = *reinterpret_cast<const float4*>(
                    Xb + (nn * 16 + ngrp) * XSTRIDE + kkg * 4);
#pragma unroll
            for (int j = 0; j < 4; j++) {
                float4 w = *reinterpret_cast<const float4*>(
                    Ws + (c * 32 + kkg * 4 + j) * 64 + fgrp * 4);
#pragma unroll
                for (int nn = 0; nn < 8; nn++) {
                    float xs = (j == 0) ? xr[nn].x : (j == 1) ? xr[nn].y
                             : (j == 2) ? xr[nn].z : xr[nn].w;
                    acc[nn].x += xs * w.x; acc[nn].y += xs * w.y;
                    acc[nn].z += xs * w.z; acc[nn].w += xs * w.w;
                }
            }
        }
        __syncthreads();
    }

#pragma unroll
    for (int nn = 0; nn < 8; nn++) {
        int n = nodeBase + nn * 16 + ngrp;
        if (n < N_NODES) {
            union { __half2 h[2]; uint2 u; } pk;
            pk.h[0] = __floats2half2_rn(acc[nn].x, acc[nn].y);
            pk.h[1] = __floats2half2_rn(acc[nn].z, acc[nn].w);
            *reinterpret_cast<uint2*>(out + (size_t)n * 64 + fgrp * 4) = pk.u;
        }
    }
}

// ------------------------- CSR build --------------------------------------
__global__ void k_zero_cnt() {
    int i = blockIdx.x * blockDim.x + threadIdx.x;
    if (i < N_NODES) g_cnt[i] = 0;
}

__global__ void k_hist(const int* __restrict__ ei) {
    int e = blockIdx.x * blockDim.x + threadIdx.x;
    if (e < N_EDGES) atomicAdd(&g_cnt[ei[N_EDGES + e]], 1);
}

// per-block inclusive scan of g_cnt -> g_rowptr[i+1]; also dinv = rsqrt(cnt+1)
__global__ void k_scan1() {
    __shared__ int wsum[32];
    int i = blockIdx.x * 1024 + threadIdx.x;
    int lane = threadIdx.x & 31, wid = threadIdx.x >> 5;
    int v = (i < N_NODES) ? g_cnt[i] : 0;
    if (i < N_NODES) g_dinv[i] = rsqrtf((float)v + 1.0f);
    int sv = v;
#pragma unroll
    for (int d = 1; d < 32; d <<= 1) {
        int t = __shfl_up_sync(0xffffffffu, sv, d);
        if (lane >= d) sv += t;
    }
    if (lane == 31) wsum[wid] = sv;
    __syncthreads();
    if (wid == 0) {
        int wv = wsum[lane];
#pragma unroll
        for (int d = 1; d < 32; d <<= 1) {
            int t = __shfl_up_sync(0xffffffffu, wv, d);
            if (lane >= d) wv += t;
        }
        wsum[lane] = wv;
    }
    __syncthreads();
    int incl = sv + (wid > 0 ? wsum[wid - 1] : 0);
    if (i < N_NODES) g_rowptr[i + 1] = incl;
    if (threadIdx.x == 1023) g_blksum[blockIdx.x] = incl;
}

__global__ void k_scan2(int nb) {
    __shared__ int wsum[4];
    int b = threadIdx.x;
    int lane = b & 31, wid = b >> 5;
    int v = (b < nb) ? g_blksum[b] : 0;
    int sv = v;
#pragma unroll
    for (int d = 1; d < 32; d <<= 1) {
        int t = __shfl_up_sync(0xffffffffu, sv, d);
        if (lane >= d) sv += t;
    }
    if (lane == 31) wsum[wid] = sv;
    __syncthreads();
    if (b == 0) {
        int run = 0;
#pragma unroll
        for (int w = 0; w < 4; w++) { int t = wsum[w]; wsum[w] = run; run += t; }
    }
    __syncthreads();
    int excl = sv + wsum[wid] - v;
    if (b < nb) g_blksum[b] = excl;
}

// finalize rowptr AND init cursor
__global__ void k_scan3() {
    int i = blockIdx.x * blockDim.x + threadIdx.x;
    if (i < N_NODES) {
        int rp = g_rowptr[i + 1] + g_blksum[i >> 10];
        g_rowptr[i + 1] = rp;
        if (i + 1 < N_NODES) g_cursor[i + 1] = rp;
    }
    if (i == 0) { g_rowptr[0] = 0; g_cursor[0] = 0; }
}

__global__ void k_fill(const int* __restrict__ ei) {
    int e = blockIdx.x * blockDim.x + threadIdx.x;
    if (e >= N_EDGES) return;
    int s = ei[e];
    int d = ei[N_EDGES + e];
    int pos = atomicAdd(&g_cursor[d], 1);
    float w = g_dinv[s] * g_dinv[d];
    g_epair[pos] = make_int2(s, __float_as_int(w));
}

// ------------------------- fused gather + self + BN + ReLU (+ head) --------
// One warp per node; h is fp16 (__half2 per lane = feats 2l, 2l+1); fp32 accum.
// 16-edge descriptor prefetch keeps 16 row loads in flight.
template <bool HEAD>
__global__ void k_gather(const __half* __restrict__ h,
                         const float* __restrict__ bb, const float* __restrict__ gg,
                         const float* __restrict__ be, const float* __restrict__ mm,
                         const float* __restrict__ vv,
                         const float* __restrict__ Wc1, const float* __restrict__ bc1,
                         const float* __restrict__ Wc2, const float* __restrict__ bc2,
                         float* __restrict__ out) {
    __shared__ float W1s[64 * 32];
    int tid = threadIdx.x, lane = tid & 31, warp = tid >> 5;
    if (HEAD) {
        for (int i = tid; i < 64 * 32; i += 256) W1s[i] = Wc1[i];
        __syncthreads();
    }
    int n = blockIdx.x * 8 + warp;
    if (n >= N_NODES) return;

    const __half2* __restrict__ h2 = reinterpret_cast<const __half2*>(h);
    int beg = g_rowptr[n], end = g_rowptr[n + 1];
    float di = g_dinv[n];

    float2 hv = __half22float2(__ldg(h2 + (size_t)n * 32 + lane));
    float accx = di * di * hv.x;
    float accy = di * di * hv.y;

    for (int p = beg; p < end; p += 16) {
        int2 eb[16];
#pragma unroll
        for (int j = 0; j < 16; j++) {
            int idx = p + j;
            eb[j] = (idx < end) ? __ldg(&g_epair[idx]) : make_int2(0, 0);
        }
#pragma unroll
        for (int j = 0; j < 16; j++) {
            float w = __int_as_float(eb[j].y);
            float2 hs = __half22float2(__ldg(h2 + (size_t)eb[j].x * 32 + lane));
            accx += w * hs.x;
            accy += w * hs.y;
        }
    }

    int f0 = 2 * lane, f1 = 2 * lane + 1;
    float sc0 = __ldg(gg + f0) * rsqrtf(__ldg(vv + f0) + BN_EPS);
    float sc1 = __ldg(gg + f1) * rsqrtf(__ldg(vv + f1) + BN_EPS);
    float val0 = fmaxf((accx + __ldg(bb + f0) - __ldg(mm + f0)) * sc0 + __ldg(be + f0), 0.0f);
    float val1 = fmaxf((accy + __ldg(bb + f1) - __ldg(mm + f1)) * sc1 + __ldg(be + f1), 0.0f);

    if (!HEAD) {
        reinterpret_cast<float2*>(out)[(size_t)n * 32 + lane] = make_float2(val0, val1);
    } else {
        float a = __ldg(bc1 + lane);
#pragma unroll
        for (int k = 0; k < 32; k++) {
            a += __shfl_sync(0xffffffffu, val0, k) * W1s[(2 * k)     * 32 + lane];
            a += __shfl_sync(0xffffffffu, val1, k) * W1s[(2 * k + 1) * 32 + lane];
        }
        float mid = fmaxf(a, 0.0f);
        float pp = mid * __ldg(Wc2 + lane);
#pragma unroll
        for (int off = 16; off; off >>= 1)
            pp += __shfl_xor_sync(0xffffffffu, pp, off);
        if (lane == 0)
            out[n] = 1.0f / (1.0f + expf(-(pp + __ldg(bc2))));
    }
}

// ---------------------------------------------------------------------------
extern "C" void kernel_launch(void* const* d_in, const int* in_sizes, int n_in,
                              void* d_out, int out_size) {
    const float* x   = (const float*)d_in[0];
    const int*   ei  = (const int*)  d_in[1];
    const float* W1  = (const float*)d_in[2];
    const float* b1  = (const float*)d_in[3];
    const float* g1  = (const float*)d_in[4];
    const float* be1 = (const float*)d_in[5];
    const float* m1  = (const float*)d_in[6];
    const float* v1  = (const float*)d_in[7];
    const float* W2  = (const float*)d_in[8];
    const float* b2  = (const float*)d_in[9];
    const float* g2  = (const float*)d_in[10];
    const float* be2 = (const float*)d_in[11];
    const float* m2  = (const float*)d_in[12];
    const float* v2  = (const float*)d_in[13];
    const float* Wc1 = (const float*)d_in[14];
    const float* bc1 = (const float*)d_in[15];
    const float* Wc2 = (const float*)d_in[16];
    const float* bc2 = (const float*)d_in[17];
    float* out = (float*)d_out;

    __half* bufH;  cudaGetSymbolAddress((void**)&bufH, g_bufH);
    float*  bufF;  cudaGetSymbolAddress((void**)&bufF, g_bufF);

    static cudaStream_t s_side = nullptr;
    static cudaEvent_t  s_fork = nullptr, s_join = nullptr;
    if (s_side == nullptr) {
        cudaStreamCreateWithFlags(&s_side, cudaStreamNonBlocking);
        cudaEventCreateWithFlags(&s_fork, cudaEventDisableTiming);
        cudaEventCreateWithFlags(&s_join, cudaEventDisableTiming);
    }

    const int nodeBlocks = (N_NODES + 255) / 256;            // 391
    const int edgeBlocks = (N_EDGES + 255) / 256;            // 6250
    const int scanBlocks = (N_NODES + 1023) / 1024;          // 98
    const int gemmBlocks = (N_NODES + 127) / 128;            // 782
    const int gathBlocks = (N_NODES + 7) / 8;                // 12500

    const int smem1 = (F_IN  * 64 + 2 * 128 * XSTRIDE) * 4;  // 69632 B
    const int smem2 = (F_HID * 64 + 2 * 128 * XSTRIDE) * 4;  // 53248 B
    cudaFuncSetAttribute(k_gemm<F_IN>,
                         cudaFuncAttributeMaxDynamicSharedMemorySize, smem1);
    cudaFuncSetAttribute(k_gemm<F_HID>,
                         cudaFuncAttributeMaxDynamicSharedMemorySize, smem2);

    // Fork: gemm1 (needs only x,W1) concurrent with CSR build.
    cudaEventRecord(s_fork, 0);
    cudaStreamWaitEvent(s_side, s_fork, 0);
    k_gemm<F_IN><<<gemmBlocks, 256, smem1, s_side>>>(x, W1, bufH);
    cudaEventRecord(s_join, s_side);

    // Main branch: CSR build
    k_zero_cnt<<<nodeBlocks, 256>>>();
    k_hist<<<edgeBlocks, 256>>>(ei);
    k_scan1<<<scanBlocks, 1024>>>();
    k_scan2<<<1, 128>>>(scanBlocks);
    k_scan3<<<nodeBlocks, 256>>>();
    k_fill<<<edgeBlocks, 256>>>(ei);

    cudaStreamWaitEvent(0, s_join, 0);

    // layer 1 aggregation (h1 fp16 -> z1 fp32)
    k_gather<false><<<gathBlocks, 256>>>(bufH, b1, g1, be1, m1, v1,
                                         nullptr, nullptr, nullptr, nullptr, bufF);
    // layer 2 (z1 fp32 -> h2 fp16), then gather + head
    k_gemm<F_HID><<<gemmBlocks, 256, smem2>>>(bufF, W2, bufH);
    k_gather<true><<<gathBlocks, 256>>>(bufH, b2, g2, be2, m2, v2,
                                        Wc1, bc1, Wc2, bc2, out);
}

// round 11
// speedup vs baseline: 1.0968x; 1.0047x over previous
#include <cuda_runtime.h>
#include <cuda_fp16.h>
#include <math.h>

#define N_NODES 100000
#define N_EDGES 1600000
#define F_IN    128
#define F_HID   64
#define BN_EPS  1e-5f

// ------------------------- scratch (__device__ globals) --------------------
__device__ __half g_bufH[(size_t)N_NODES * F_HID];  // 12.8 MB: h1 / h2 (fp16)
__device__ float  g_bufF[(size_t)N_NODES * F_HID];  // 25.6 MB: z1 (fp32)
__device__ float  g_dinv[N_NODES];
__device__ int    g_cnt[N_NODES];                   // .bss => zeroed at load;
                                                    // k_scan1 re-zeroes per run
__device__ int    g_rowptr[N_NODES + 1];
__device__ int    g_cursor[N_NODES];
__device__ int2   g_epair[N_EDGES];                 // (src, norm-as-int)
__device__ int    g_blksum[128];

// ------------------------- cp.async helpers --------------------------------
__device__ __forceinline__ void cp_async16(void* smem_dst, const void* gmem_src) {
    unsigned s = (unsigned)__cvta_generic_to_shared(smem_dst);
    asm volatile("cp.async.cg.shared.global [%0], [%1], 16;\n"
                 :: "r"(s), "l"(gmem_src));
}
__device__ __forceinline__ void cp_commit() {
    asm volatile("cp.async.commit_group;\n");
}
template <int N>
__device__ __forceinline__ void cp_wait() {
    asm volatile("cp.async.wait_group %0;\n" :: "n"(N));
}

// ------------------------- GEMM: out[N,64] = x[N,KDIM] @ W[KDIM,64] --------
// fp32 inputs, fp16 output. 256 threads/block, tile 128 nodes x 64 feats;
// thread = 8 nodes x 4 feats. W staged whole once; X chunks double-buffered
// via cp.async. Dynamic smem.
#define XSTRIDE 36

template <int KDIM>
__global__ void __launch_bounds__(256, 3)
k_gemm(const float* __restrict__ x, const float* __restrict__ W,
       __half* __restrict__ out) {
    extern __shared__ __align__(16) float smem[];
    float* Ws  = smem;                        // KDIM*64 floats
    float* Xs0 = smem + KDIM * 64;            // 128*XSTRIDE
    float* Xs1 = Xs0 + 128 * XSTRIDE;

    const int C = KDIM / 32;                  // k-chunks
    int tid  = threadIdx.x;
    int fgrp = tid & 15;                      // 16 feat groups x 4 feats
    int ngrp = tid >> 4;                      // 16 node groups
    int nodeBase = blockIdx.x * 128;

    float4 acc[8];
#pragma unroll
    for (int a = 0; a < 8; a++) acc[a] = make_float4(0.f, 0.f, 0.f, 0.f);

    // prefetch X chunk 0 + all of W (one group)
    {
        float* Xb = Xs0;
#pragma unroll
        for (int t = 0; t < 4; t++) {
            int i = t * 256 + tid;
            int node = i >> 3, q = i & 7;
            int gn = nodeBase + node;
            if (gn >= N_NODES) gn = N_NODES - 1;
            cp_async16(Xb + node * XSTRIDE + q * 4,
                       x + (size_t)gn * KDIM + q * 4);
        }
        for (int i = tid; i < KDIM * 16; i += 256)
            cp_async16(Ws + i * 4, W + i * 4);
        cp_commit();
    }

    for (int c = 0; c < C; c++) {
        if (c + 1 < C) {                       // prefetch next chunk
            float* Xb = ((c + 1) & 1) ? Xs1 : Xs0;
#pragma unroll
            for (int t = 0; t < 4; t++) {
                int i = t * 256 + tid;
                int node = i >> 3, q = i & 7;
                int gn = nodeBase + node;
                if (gn >= N_NODES) gn = N_NODES - 1;
                cp_async16(Xb + node * XSTRIDE + q * 4,
                           x + (size_t)gn * KDIM + (c + 1) * 32 + q * 4);
            }
            cp_commit();
            cp_wait<1>();
        } else {
            cp_wait<0>();
        }
        __syncthreads();

        const float* Xb = (c & 1) ? Xs1 : Xs0;
#pragma unroll
        for (int kkg = 0; kkg < 8; kkg++) {
            float4 xr[8];
#pragma unroll
            for (int nn = 0; nn < 8; nn++)
                xr[nn] = *reinterpret_cast<const float4*>(
                    Xb + (nn * 16 + ngrp) * XSTRIDE + kkg * 4);
#pragma unroll
            for (int j = 0; j < 4; j++) {
                float4 w = *reinterpret_cast<const float4*>(
                    Ws + (c * 32 + kkg * 4 + j) * 64 + fgrp * 4);
#pragma unroll
                for (int nn = 0; nn < 8; nn++) {
                    float xs = (j == 0) ? xr[nn].x : (j == 1) ? xr[nn].y
                             : (j == 2) ? xr[nn].z : xr[nn].w;
                    acc[nn].x += xs * w.x; acc[nn].y += xs * w.y;
                    acc[nn].z += xs * w.z; acc[nn].w += xs * w.w;
                }
            }
        }
        __syncthreads();
    }

#pragma unroll
    for (int nn = 0; nn < 8; nn++) {
        int n = nodeBase + nn * 16 + ngrp;
        if (n < N_NODES) {
            union { __half2 h[2]; uint2 u; } pk;
            pk.h[0] = __floats2half2_rn(acc[nn].x, acc[nn].y);
            pk.h[1] = __floats2half2_rn(acc[nn].z, acc[nn].w);
            *reinterpret_cast<uint2*>(out + (size_t)n * 64 + fgrp * 4) = pk.u;
        }
    }
}

// ------------------------- CSR build --------------------------------------
__global__ void k_hist(const int* __restrict__ ei) {
    int e = blockIdx.x * blockDim.x + threadIdx.x;
    if (e < N_EDGES) atomicAdd(&g_cnt[ei[N_EDGES + e]], 1);
}

// per-block inclusive scan of g_cnt -> g_rowptr[i+1]; also dinv = rsqrt(cnt+1);
// re-zeroes g_cnt for the next graph replay (first run sees .bss zeros).
__global__ void k_scan1() {
    __shared__ int wsum[32];
    int i = blockIdx.x * 1024 + threadIdx.x;
    int lane = threadIdx.x & 31, wid = threadIdx.x >> 5;
    int v = 0;
    if (i < N_NODES) {
        v = g_cnt[i];
        g_cnt[i] = 0;                          // reset for next replay
        g_dinv[i] = rsqrtf((float)v + 1.0f);
    }
    int sv = v;
#pragma unroll
    for (int d = 1; d < 32; d <<= 1) {
        int t = __shfl_up_sync(0xffffffffu, sv, d);
        if (lane >= d) sv += t;
    }
    if (lane == 31) wsum[wid] = sv;
    __syncthreads();
    if (wid == 0) {
        int wv = wsum[lane];
#pragma unroll
        for (int d = 1; d < 32; d <<= 1) {
            int t = __shfl_up_sync(0xffffffffu, wv, d);
            if (lane >= d) wv += t;
        }
        wsum[lane] = wv;
    }
    __syncthreads();
    int incl = sv + (wid > 0 ? wsum[wid - 1] : 0);
    if (i < N_NODES) g_rowptr[i + 1] = incl;
    if (threadIdx.x == 1023) g_blksum[blockIdx.x] = incl;
}

__global__ void k_scan2(int nb) {
    __shared__ int wsum[4];
    int b = threadIdx.x;
    int lane = b & 31, wid = b >> 5;
    int v = (b < nb) ? g_blksum[b] : 0;
    int sv = v;
#pragma unroll
    for (int d = 1; d < 32; d <<= 1) {
        int t = __shfl_up_sync(0xffffffffu, sv, d);
        if (lane >= d) sv += t;
    }
    if (lane == 31) wsum[wid] = sv;
    __syncthreads();
    if (b == 0) {
        int run = 0;
#pragma unroll
        for (int w = 0; w < 4; w++) { int t = wsum[w]; wsum[w] = run; run += t; }
    }
    __syncthreads();
    int excl = sv + wsum[wid] - v;
    if (b < nb) g_blksum[b] = excl;
}

// finalize rowptr AND init cursor
__global__ void k_scan3() {
    int i = blockIdx.x * blockDim.x + threadIdx.x;
    if (i < N_NODES) {
        int rp = g_rowptr[i + 1] + g_blksum[i >> 10];
        g_rowptr[i + 1] = rp;
        if (i + 1 < N_NODES) g_cursor[i + 1] = rp;
    }
    if (i == 0) { g_rowptr[0] = 0; g_cursor[0] = 0; }
}

__global__ void k_fill(const int* __restrict__ ei) {
    int e = blockIdx.x * blockDim.x + threadIdx.x;
    if (e >= N_EDGES) return;
    int s = ei[e];
    int d = ei[N_EDGES + e];
    int pos = atomicAdd(&g_cursor[d], 1);
    float w = g_dinv[s] * g_dinv[d];
    g_epair[pos] = make_int2(s, __float_as_int(w));
}

// ------------------------- fused gather + self + BN + ReLU (+ head) --------
// Grid-strided warps: each warp loops over nodes (stride = total warps).
// HEAD: W1s staged once per BLOCK (1184 blocks -> 9.5MB, was 12500 -> 100MB).
// h fp16 (__half2 per lane = feats 2l,2l+1); fp32 accum; 16-edge prefetch.
#define GATH_BLOCKS 1184

template <bool HEAD>
__global__ void k_gather(const __half* __restrict__ h,
                         const float* __restrict__ bb, const float* __restrict__ gg,
                         const float* __restrict__ be, const float* __restrict__ mm,
                         const float* __restrict__ vv,
                         const float* __restrict__ Wc1, const float* __restrict__ bc1,
                         const float* __restrict__ Wc2, const float* __restrict__ bc2,
                         float* __restrict__ out) {
    __shared__ float W1s[64 * 32];
    int tid = threadIdx.x, lane = tid & 31, warp = tid >> 5;
    if (HEAD) {
        for (int i = tid; i < 64 * 32; i += 256) W1s[i] = Wc1[i];
        __syncthreads();
    }

    const __half2* __restrict__ h2 = reinterpret_cast<const __half2*>(h);
    int gw = blockIdx.x * 8 + warp;
    const int nwarps = GATH_BLOCKS * 8;

    for (int n = gw; n < N_NODES; n += nwarps) {
        int beg = g_rowptr[n], end = g_rowptr[n + 1];
        float di = g_dinv[n];

        float2 hv = __half22float2(__ldg(h2 + (size_t)n * 32 + lane));
        float accx = di * di * hv.x;
        float accy = di * di * hv.y;

        for (int p = beg; p < end; p += 16) {
            int2 eb[16];
#pragma unroll
            for (int j = 0; j < 16; j++) {
                int idx = p + j;
                eb[j] = (idx < end) ? __ldg(&g_epair[idx]) : make_int2(0, 0);
            }
#pragma unroll
            for (int j = 0; j < 16; j++) {
                float w = __int_as_float(eb[j].y);
                float2 hs = __half22float2(__ldg(h2 + (size_t)eb[j].x * 32 + lane));
                accx += w * hs.x;
                accy += w * hs.y;
            }
        }

        int f0 = 2 * lane, f1 = 2 * lane + 1;
        float sc0 = __ldg(gg + f0) * rsqrtf(__ldg(vv + f0) + BN_EPS);
        float sc1 = __ldg(gg + f1) * rsqrtf(__ldg(vv + f1) + BN_EPS);
        float val0 = fmaxf((accx + __ldg(bb + f0) - __ldg(mm + f0)) * sc0 + __ldg(be + f0), 0.0f);
        float val1 = fmaxf((accy + __ldg(bb + f1) - __ldg(mm + f1)) * sc1 + __ldg(be + f1), 0.0f);

        if (!HEAD) {
            reinterpret_cast<float2*>(out)[(size_t)n * 32 + lane] = make_float2(val0, val1);
        } else {
            float a = __ldg(bc1 + lane);
#pragma unroll
            for (int k = 0; k < 32; k++) {
                a += __shfl_sync(0xffffffffu, val0, k) * W1s[(2 * k)     * 32 + lane];
                a += __shfl_sync(0xffffffffu, val1, k) * W1s[(2 * k + 1) * 32 + lane];
            }
            float mid = fmaxf(a, 0.0f);
            float pp = mid * __ldg(Wc2 + lane);
#pragma unroll
            for (int off = 16; off; off >>= 1)
                pp += __shfl_xor_sync(0xffffffffu, pp, off);
            if (lane == 0)
                out[n] = 1.0f / (1.0f + expf(-(pp + __ldg(bc2))));
        }
    }
}

// ---------------------------------------------------------------------------
extern "C" void kernel_launch(void* const* d_in, const int* in_sizes, int n_in,
                              void* d_out, int out_size) {
    const float* x   = (const float*)d_in[0];
    const int*   ei  = (const int*)  d_in[1];
    const float* W1  = (const float*)d_in[2];
    const float* b1  = (const float*)d_in[3];
    const float* g1  = (const float*)d_in[4];
    const float* be1 = (const float*)d_in[5];
    const float* m1  = (const float*)d_in[6];
    const float* v1  = (const float*)d_in[7];
    const float* W2  = (const float*)d_in[8];
    const float* b2  = (const float*)d_in[9];
    const float* g2  = (const float*)d_in[10];
    const float* be2 = (const float*)d_in[11];
    const float* m2  = (const float*)d_in[12];
    const float* v2  = (const float*)d_in[13];
    const float* Wc1 = (const float*)d_in[14];
    const float* bc1 = (const float*)d_in[15];
    const float* Wc2 = (const float*)d_in[16];
    const float* bc2 = (const float*)d_in[17];
    float* out = (float*)d_out;

    __half* bufH;  cudaGetSymbolAddress((void**)&bufH, g_bufH);
    float*  bufF;  cudaGetSymbolAddress((void**)&bufF, g_bufF);

    static cudaStream_t s_side = nullptr;
    static cudaEvent_t  s_fork = nullptr, s_join = nullptr;
    if (s_side == nullptr) {
        cudaStreamCreateWithFlags(&s_side, cudaStreamNonBlocking);
        cudaEventCreateWithFlags(&s_fork, cudaEventDisableTiming);
        cudaEventCreateWithFlags(&s_join, cudaEventDisableTiming);
    }

    const int nodeBlocks = (N_NODES + 255) / 256;            // 391
    const int edgeBlocks = (N_EDGES + 255) / 256;            // 6250
    const int scanBlocks = (N_NODES + 1023) / 1024;          // 98
    const int gemmBlocks = (N_NODES + 127) / 128;            // 782

    const int smem1 = (F_IN  * 64 + 2 * 128 * XSTRIDE) * 4;  // 69632 B
    const int smem2 = (F_HID * 64 + 2 * 128 * XSTRIDE) * 4;  // 53248 B
    cudaFuncSetAttribute(k_gemm<F_IN>,
                         cudaFuncAttributeMaxDynamicSharedMemorySize, smem1);
    cudaFuncSetAttribute(k_gemm<F_HID>,
                         cudaFuncAttributeMaxDynamicSharedMemorySize, smem2);

    // Fork: gemm1 (needs only x,W1) concurrent with CSR build.
    cudaEventRecord(s_fork, 0);
    cudaStreamWaitEvent(s_side, s_fork, 0);
    k_gemm<F_IN><<<gemmBlocks, 256, smem1, s_side>>>(x, W1, bufH);
    cudaEventRecord(s_join, s_side);

    // Main branch: CSR build (g_cnt pre-zeroed: .bss on first run, scan1 after)
    k_hist<<<edgeBlocks, 256>>>(ei);
    k_scan1<<<scanBlocks, 1024>>>();
    k_scan2<<<1, 128>>>(scanBlocks);
    k_scan3<<<nodeBlocks, 256>>>();
    k_fill<<<edgeBlocks, 256>>>(ei);

    cudaStreamWaitEvent(0, s_join, 0);

    // layer 1 aggregation (h1 fp16 -> z1 fp32)
    k_gather<false><<<GATH_BLOCKS, 256>>>(bufH, b1, g1, be1, m1, v1,
                                          nullptr, nullptr, nullptr, nullptr, bufF);
    // layer 2 (z1 fp32 -> h2 fp16), then gather + head
    k_gemm<F_HID><<<gemmBlocks, 256, smem2>>>(bufF, W2, bufH);
    k_gather<true><<<GATH_BLOCKS, 256>>>(bufH, b2, g2, be2, m2, v2,
                                         Wc1, bc1, Wc2, bc2, out);
}

// round 14
// speedup vs baseline: 1.0987x; 1.0018x over previous
#include <cuda_runtime.h>
#include <cuda_fp16.h>
#include <math.h>

#define N_NODES 100000
#define N_EDGES 1600000
#define F_IN    128
#define F_HID   64
#define BN_EPS  1e-5f

// ------------------------- scratch (__device__ globals) --------------------
__device__ __half g_bufH[(size_t)N_NODES * F_HID];  // 12.8 MB: h1 / h2 (fp16)
__device__ float  g_bufF[(size_t)N_NODES * F_HID];  // 25.6 MB: z1 (fp32)
__device__ float  g_dinv[N_NODES];
__device__ int    g_cnt[N_NODES];                   // .bss zeroed; scan1 re-zeroes
__device__ int    g_rowptr[N_NODES + 1];
__device__ int    g_cursor[N_NODES];
__device__ int2   g_epair[N_EDGES];                 // (src, norm-as-int)
__device__ int    g_blksum[128];

// ------------------------- cp.async helpers --------------------------------
__device__ __forceinline__ void cp_async16(void* smem_dst, const void* gmem_src) {
    unsigned s = (unsigned)__cvta_generic_to_shared(smem_dst);
    asm volatile("cp.async.cg.shared.global [%0], [%1], 16;\n"
                 :: "r"(s), "l"(gmem_src));
}
__device__ __forceinline__ void cp_commit() {
    asm volatile("cp.async.commit_group;\n");
}
template <int N>
__device__ __forceinline__ void cp_wait() {
    asm volatile("cp.async.wait_group %0;\n" :: "n"(N));
}

// ------------------------- GEMM: out[N,64] = x[N,KDIM] @ W[KDIM,64] --------
// unchanged (measured best): fp32 in, fp16 out, cp.async double-buffer.
#define XSTRIDE 36

template <int KDIM>
__global__ void __launch_bounds__(256, 3)
k_gemm(const float* __restrict__ x, const float* __restrict__ W,
       __half* __restrict__ out) {
    extern __shared__ __align__(16) float smem[];
    float* Ws  = smem;
    float* Xs0 = smem + KDIM * 64;
    float* Xs1 = Xs0 + 128 * XSTRIDE;

    const int C = KDIM / 32;
    int tid  = threadIdx.x;
    int fgrp = tid & 15;
    int ngrp = tid >> 4;
    int nodeBase = blockIdx.x * 128;

    float4 acc[8];
#pragma unroll
    for (int a = 0; a < 8; a++) acc[a] = make_float4(0.f, 0.f, 0.f, 0.f);

    {
        float* Xb = Xs0;
#pragma unroll
        for (int t = 0; t < 4; t++) {
            int i = t * 256 + tid;
            int node = i >> 3, q = i & 7;
            int gn = nodeBase + node;
            if (gn >= N_NODES) gn = N_NODES - 1;
            cp_async16(Xb + node * XSTRIDE + q * 4,
                       x + (size_t)gn * KDIM + q * 4);
        }
        for (int i = tid; i < KDIM * 16; i += 256)
            cp_async16(Ws + i * 4, W + i * 4);
        cp_commit();
    }

    for (int c = 0; c < C; c++) {
        if (c + 1 < C) {
            float* Xb = ((c + 1) & 1) ? Xs1 : Xs0;
#pragma unroll
            for (int t = 0; t < 4; t++) {
                int i = t * 256 + tid;
                int node = i >> 3, q = i & 7;
                int gn = nodeBase + node;
                if (gn >= N_NODES) gn = N_NODES - 1;
                cp_async16(Xb + node * XSTRIDE + q * 4,
                           x + (size_t)gn * KDIM + (c + 1) * 32 + q * 4);
            }
            cp_commit();
            cp_wait<1>();
        } else {
            cp_wait<0>();
        }
        __syncthreads();

        const float* Xb = (c & 1) ? Xs1 : Xs0;
#pragma unroll
        for (int kkg = 0; kkg < 8; kkg++) {
            float4 xr[8];
#pragma unroll
            for (int nn = 0; nn < 8; nn++)
                xr[nn] = *reinterpret_cast<const float4*>(
                    Xb + (nn * 16 + ngrp) * XSTRIDE + kkg * 4);
#pragma unroll
            for (int j = 0; j < 4; j++) {
                float4 w = *reinterpret_cast<const float4*>(
                    Ws + (c * 32 + kkg * 4 + j) * 64 + fgrp * 4);
#pragma unroll
                for (int nn = 0; nn < 8; nn++) {
                    float xs = (j == 0) ? xr[nn].x : (j == 1) ? xr[nn].y
                             : (j == 2) ? xr[nn].z : xr[nn].w;
                    acc[nn].x += xs * w.x; acc[nn].y += xs * w.y;
                    acc[nn].z += xs * w.z; acc[nn].w += xs * w.w;
                }
            }
        }
        __syncthreads();
    }

#pragma unroll
    for (int nn = 0; nn < 8; nn++) {
        int n = nodeBase + nn * 16 + ngrp;
        if (n < N_NODES) {
            union { __half2 h[2]; uint2 u; } pk;
            pk.h[0] = __floats2half2_rn(acc[nn].x, acc[nn].y);
            pk.h[1] = __floats2half2_rn(acc[nn].z, acc[nn].w);
            *reinterpret_cast<uint2*>(out + (size_t)n * 64 + fgrp * 4) = pk.u;
        }
    }
}

// ------------------------- CSR build (proven 3-kernel scan) -----------------
__global__ void k_hist(const int* __restrict__ ei) {
    int e = blockIdx.x * blockDim.x + threadIdx.x;
    if (e < N_EDGES) atomicAdd(&g_cnt[ei[N_EDGES + e]], 1);
}

__global__ void k_scan1() {
    __shared__ int wsum[32];
    int i = blockIdx.x * 1024 + threadIdx.x;
    int lane = threadIdx.x & 31, wid = threadIdx.x >> 5;
    int v = 0;
    if (i < N_NODES) {
        v = g_cnt[i];
        g_cnt[i] = 0;                          // reset for next replay
        g_dinv[i] = rsqrtf((float)v + 1.0f);
    }
    int sv = v;
#pragma unroll
    for (int d = 1; d < 32; d <<= 1) {
        int t = __shfl_up_sync(0xffffffffu, sv, d);
        if (lane >= d) sv += t;
    }
    if (lane == 31) wsum[wid] = sv;
    __syncthreads();
    if (wid == 0) {
        int wv = wsum[lane];
#pragma unroll
        for (int d = 1; d < 32; d <<= 1) {
            int t = __shfl_up_sync(0xffffffffu, wv, d);
            if (lane >= d) wv += t;
        }
        wsum[lane] = wv;
    }
    __syncthreads();
    int incl = sv + (wid > 0 ? wsum[wid - 1] : 0);
    if (i < N_NODES) g_rowptr[i + 1] = incl;
    if (threadIdx.x == 1023) g_blksum[blockIdx.x] = incl;
}

__global__ void k_scan2(int nb) {
    __shared__ int wsum[4];
    int b = threadIdx.x;
    int lane = b & 31, wid = b >> 5;
    int v = (b < nb) ? g_blksum[b] : 0;
    int sv = v;
#pragma unroll
    for (int d = 1; d < 32; d <<= 1) {
        int t = __shfl_up_sync(0xffffffffu, sv, d);
        if (lane >= d) sv += t;
    }
    if (lane == 31) wsum[wid] = sv;
    __syncthreads();
    if (b == 0) {
        int run = 0;
#pragma unroll
        for (int w = 0; w < 4; w++) { int t = wsum[w]; wsum[w] = run; run += t; }
    }
    __syncthreads();
    int excl = sv + wsum[wid] - v;
    if (b < nb) g_blksum[b] = excl;
}

__global__ void k_scan3() {
    int i = blockIdx.x * blockDim.x + threadIdx.x;
    if (i < N_NODES) {
        int rp = g_rowptr[i + 1] + g_blksum[i >> 10];
        g_rowptr[i + 1] = rp;
        if (i + 1 < N_NODES) g_cursor[i + 1] = rp;
    }
    if (i == 0) { g_rowptr[0] = 0; g_cursor[0] = 0; }
}

__global__ void k_fill(const int* __restrict__ ei) {
    int e = blockIdx.x * blockDim.x + threadIdx.x;
    if (e >= N_EDGES) return;
    int s = ei[e];
    int d = ei[N_EDGES + e];
    int pos = atomicAdd(&g_cursor[d], 1);
    float w = g_dinv[s] * g_dinv[d];
    g_epair[pos] = make_int2(s, __float_as_int(w));
}

// ------------------------- fused gather + self + BN + ReLU (+ head) --------
// Grid-strided warps (R11 proven int2 descriptor path) + hoisted BN epilogue
// constants (removes ~10 LDG + 2 MUFU per node-iteration).
#define GATH_BLOCKS 1184

template <bool HEAD>
__global__ void k_gather(const __half* __restrict__ h,
                         const float* __restrict__ bb, const float* __restrict__ gg,
                         const float* __restrict__ be, const float* __restrict__ mm,
                         const float* __restrict__ vv,
                         const float* __restrict__ Wc1, const float* __restrict__ bc1,
                         const float* __restrict__ Wc2, const float* __restrict__ bc2,
                         float* __restrict__ out) {
    __shared__ float W1s[64 * 32];
    int tid = threadIdx.x, lane = tid & 31, warp = tid >> 5;
    if (HEAD) {
        for (int i = tid; i < 64 * 32; i += 256) W1s[i] = Wc1[i];
        __syncthreads();
    }

    // hoisted per-lane epilogue constants: val = max(acc*a + c, 0)
    int f0 = 2 * lane, f1 = f0 + 1;
    float a0 = __ldg(gg + f0) * rsqrtf(__ldg(vv + f0) + BN_EPS);
    float a1 = __ldg(gg + f1) * rsqrtf(__ldg(vv + f1) + BN_EPS);
    float c0 = (__ldg(bb + f0) - __ldg(mm + f0)) * a0 + __ldg(be + f0);
    float c1 = (__ldg(bb + f1) - __ldg(mm + f1)) * a1 + __ldg(be + f1);
    float wc2 = 0.f, bc1v = 0.f, bc2v = 0.f;
    if (HEAD) { wc2 = __ldg(Wc2 + lane); bc1v = __ldg(bc1 + lane); bc2v = __ldg(bc2); }

    const __half2* __restrict__ h2 = reinterpret_cast<const __half2*>(h);
    int gw = blockIdx.x * 8 + warp;
    const int nwarps = GATH_BLOCKS * 8;

    for (int n = gw; n < N_NODES; n += nwarps) {
        int beg = g_rowptr[n], end = g_rowptr[n + 1];
        float di = g_dinv[n];

        float2 hv = __half22float2(__ldg(h2 + (size_t)n * 32 + lane));
        float accx = di * di * hv.x;
        float accy = di * di * hv.y;

        for (int p = beg; p < end; p += 16) {
            int2 eb[16];
#pragma unroll
            for (int j = 0; j < 16; j++) {
                int idx = p + j;
                eb[j] = (idx < end) ? __ldg(&g_epair[idx]) : make_int2(0, 0);
            }
#pragma unroll
            for (int j = 0; j < 16; j++) {
                float w = __int_as_float(eb[j].y);
                float2 hs = __half22float2(__ldg(h2 + (size_t)eb[j].x * 32 + lane));
                accx += w * hs.x;
                accy += w * hs.y;
            }
        }

        float val0 = fmaxf(accx * a0 + c0, 0.0f);
        float val1 = fmaxf(accy * a1 + c1, 0.0f);

        if (!HEAD) {
            reinterpret_cast<float2*>(out)[(size_t)n * 32 + lane] =
                make_float2(val0, val1);
        } else {
            float a = bc1v;
#pragma unroll
            for (int k = 0; k < 32; k++) {
                a += __shfl_sync(0xffffffffu, val0, k) * W1s[(2 * k)     * 32 + lane];
                a += __shfl_sync(0xffffffffu, val1, k) * W1s[(2 * k + 1) * 32 + lane];
            }
            float mid = fmaxf(a, 0.0f);
            float pp = mid * wc2;
#pragma unroll
            for (int off = 16; off; off >>= 1)
                pp += __shfl_xor_sync(0xffffffffu, pp, off);
            if (lane == 0)
                out[n] = 1.0f / (1.0f + expf(-(pp + bc2v)));
        }
    }
}

// ---------------------------------------------------------------------------
extern "C" void kernel_launch(void* const* d_in, const int* in_sizes, int n_in,
                              void* d_out, int out_size) {
    const float* x   = (const float*)d_in[0];
    const int*   ei  = (const int*)  d_in[1];
    const float* W1  = (const float*)d_in[2];
    const float* b1  = (const float*)d_in[3];
    const float* g1  = (const float*)d_in[4];
    const float* be1 = (const float*)d_in[5];
    const float* m1  = (const float*)d_in[6];
    const float* v1  = (const float*)d_in[7];
    const float* W2  = (const float*)d_in[8];
    const float* b2  = (const float*)d_in[9];
    const float* g2  = (const float*)d_in[10];
    const float* be2 = (const float*)d_in[11];
    const float* m2  = (const float*)d_in[12];
    const float* v2  = (const float*)d_in[13];
    const float* Wc1 = (const float*)d_in[14];
    const float* bc1 = (const float*)d_in[15];
    const float* Wc2 = (const float*)d_in[16];
    const float* bc2 = (const float*)d_in[17];
    float* out = (float*)d_out;

    __half* bufH;  cudaGetSymbolAddress((void**)&bufH, g_bufH);
    float*  bufF;  cudaGetSymbolAddress((void**)&bufF, g_bufF);

    static cudaStream_t s_side = nullptr;
    static cudaEvent_t  s_fork = nullptr, s_join = nullptr;
    if (s_side == nullptr) {
        cudaStreamCreateWithFlags(&s_side, cudaStreamNonBlocking);
        cudaEventCreateWithFlags(&s_fork, cudaEventDisableTiming);
        cudaEventCreateWithFlags(&s_join, cudaEventDisableTiming);
    }

    const int nodeBlocks = (N_NODES + 255) / 256;            // 391
    const int edgeBlocks = (N_EDGES + 255) / 256;            // 6250
    const int scanBlocks = (N_NODES + 1023) / 1024;          // 98
    const int gemmBlocks = (N_NODES + 127) / 128;            // 782

    const int smem1 = (F_IN  * 64 + 2 * 128 * XSTRIDE) * 4;  // 69632 B
    const int smem2 = (F_HID * 64 + 2 * 128 * XSTRIDE) * 4;  // 53248 B
    cudaFuncSetAttribute(k_gemm<F_IN>,
                         cudaFuncAttributeMaxDynamicSharedMemorySize, smem1);
    cudaFuncSetAttribute(k_gemm<F_HID>,
                         cudaFuncAttributeMaxDynamicSharedMemorySize, smem2);

    // Fork: gemm1 (needs only x,W1) concurrent with CSR build.
    cudaEventRecord(s_fork, 0);
    cudaStreamWaitEvent(s_side, s_fork, 0);
    k_gemm<F_IN><<<gemmBlocks, 256, smem1, s_side>>>(x, W1, bufH);
    cudaEventRecord(s_join, s_side);

    // Main branch: CSR build (proven 3-kernel scan)
    k_hist<<<edgeBlocks, 256>>>(ei);
    k_scan1<<<scanBlocks, 1024>>>();
    k_scan2<<<1, 128>>>(scanBlocks);
    k_scan3<<<nodeBlocks, 256>>>();
    k_fill<<<edgeBlocks, 256>>>(ei);

    cudaStreamWaitEvent(0, s_join, 0);

    // layer 1 aggregation (h1 fp16 -> z1 fp32)
    k_gather<false><<<GATH_BLOCKS, 256>>>(bufH, b1, g1, be1, m1, v1,
                                          nullptr, nullptr, nullptr, nullptr, bufF);
    // layer 2 (z1 fp32 -> h2 fp16), then gather + head
    k_gemm<F_HID><<<gemmBlocks, 256, smem2>>>(bufF, W2, bufH);
    k_gather<true><<<GATH_BLOCKS, 256>>>(bufH, b2, g2, be2, m2, v2,
                                         Wc1, bc1, Wc2, bc2, out);
}